// round 11
// baseline (speedup 1.0000x reference)
#include <cuda_runtime.h>
#include <cstdint>

#define NIT 128
#define A_BYTES 32768            // 256 rows x 128B
#define B_BYTES 16384            // 128 rows x 128B
#define STAGE_BYTES (A_BYTES + B_BYTES)
#define SMEM_TOTAL (3*STAGE_BYTES + 128)

__device__ float g_A[(size_t)8192 * 4096];   // [gate*2048+m][k]  (k permuted, tf32, mean-removed)
__device__ float g_B[(size_t)4096 * 4096];   // [batch][k]        (k permuted, tf32)
__device__ float g_D[(size_t)8192 * 4096];   // GEMM output (pre-activations minus mean term)
__device__ float g_S[4096];                  // per-batch operand sums (fp32, unrounded)

__device__ __forceinline__ uint32_t smem_u32(const void* p) {
    uint32_t a;
    asm("{ .reg .u64 t; cvta.to.shared.u64 t, %1; cvt.u32.u64 %0, t; }" : "=r"(a) : "l"(p));
    return a;
}
__device__ __forceinline__ float rna_tf32(float v) {
    float r; asm("cvt.rna.tf32.f32 %0, %1;" : "=f"(r) : "f"(v)); return r;
}
__device__ __forceinline__ float sigmf(float z) { return 1.0f / (1.0f + __expf(-z)); }

// ---------------- pre-pass kernels ----------------
// Stored-k permutation: within each 8-group, logical order (0,4,1,5,2,6,3,7),
// so mma tf32 fragments (cols c and c+4) become one LDS.64.

__global__ void convA(const float* __restrict__ a0, const float* __restrict__ a1,
                      const float* __restrict__ a2, const float* __restrict__ a3,
                      const float* __restrict__ h0, const float* __restrict__ h1,
                      const float* __restrict__ h2, const float* __restrict__ h3) {
    size_t i4 = (size_t)blockIdx.x * 256 + threadIdx.x;      // 8388608 float4s
    size_t flat = i4 << 2;
    int g = (int)(flat >> 23);
    int rem = (int)(flat & ((1u << 23) - 1));
    int m = rem >> 12;
    int p0 = rem & 4095;
    const float* w = (p0 < 2048)
        ? ((g == 0) ? a0 : (g == 1) ? a1 : (g == 2) ? a2 : a3)
        : ((g == 0) ? h0 : (g == 1) ? h1 : (g == 2) ? h2 : h3);
    int off = ((p0 & 2047) & ~7) + ((p0 & 4) >> 1);
    const float* src = w + (size_t)m * 2048 + off;
    float2 lo = *(const float2*)src;
    float2 hi = *(const float2*)(src + 4);
    float4 o;
    o.x = rna_tf32(lo.x - 0.2f); o.y = rna_tf32(hi.x - 0.2f);
    o.z = rna_tf32(lo.y - 0.2f); o.w = rna_tf32(hi.y - 0.2f);
    *(float4*)(g_A + flat) = o;
}

__global__ void convBh(const float* __restrict__ h) {
    size_t i4 = (size_t)blockIdx.x * 256 + threadIdx.x;      // 2097152 float4s
    size_t n = i4 >> 9;
    int p0 = (int)(i4 & 511) << 2;
    int off = (p0 & ~7) + ((p0 & 4) >> 1);
    const float* src = h + n * 2048 + off;
    float2 lo = *(const float2*)src;
    float2 hi = *(const float2*)(src + 4);
    float4 o;
    o.x = rna_tf32(lo.x); o.y = rna_tf32(hi.x);
    o.z = rna_tf32(lo.y); o.w = rna_tf32(hi.y);
    *(float4*)(g_B + n * 4096 + 2048 + p0) = o;
}

__global__ void convBx(const float* __restrict__ x) {     // x [2048, 4096] -> transpose
    __shared__ float t[32][33];
    int b0 = blockIdx.x << 5, k0 = blockIdx.y << 5;
    int tx = threadIdx.x, ty = threadIdx.y;
#pragma unroll
    for (int i = 0; i < 4; ++i)
        t[ty + i * 8][tx] = rna_tf32(x[(size_t)(k0 + ty + i * 8) * 4096 + b0 + tx]);
    __syncthreads();
    int l = (tx & ~7) + ((tx & 7) >> 1) + ((tx & 1) << 2); // logical k for stored pos tx
#pragma unroll
    for (int i = 0; i < 4; ++i) {
        int row = ty + i * 8;
        g_B[(size_t)(b0 + row) * 4096 + k0 + tx] = t[l][row];
    }
}

// S[n] = sum_k x[k][n] + sum_j h[n][j]  (fp32, from unrounded inputs)
__global__ void sumX(const float* __restrict__ x) {
    int n = blockIdx.x * 256 + threadIdx.x;
    float s[8] = {0, 0, 0, 0, 0, 0, 0, 0};
    for (int k = 0; k < 2048; k += 8)
#pragma unroll
        for (int j = 0; j < 8; ++j) s[j] += x[(size_t)(k + j) * 4096 + n];
    g_S[n] = ((s[0] + s[1]) + (s[2] + s[3])) + ((s[4] + s[5]) + (s[6] + s[7]));
}
__global__ void sumH(const float* __restrict__ h) {
    __shared__ float red[256];
    const float* hr = h + (size_t)blockIdx.x * 2048;
    float s = 0.0f;
    for (int i = threadIdx.x; i < 512; i += 256) {
        float4 v = *(const float4*)(hr + i * 4);
        s += (v.x + v.y) + (v.z + v.w);
    }
    red[threadIdx.x] = s; __syncthreads();
    for (int st = 128; st > 0; st >>= 1) {
        if (threadIdx.x < st) red[threadIdx.x] += red[threadIdx.x + st];
        __syncthreads();
    }
    if (threadIdx.x == 0) g_S[blockIdx.x] += red[0];
}

// ---------------- tf32 mma.sync GEMM: D = A_cat @ B_cat^T ----------------
#define LOAD_STAGE(stg, itn) do { \
    uint32_t db_ = sbase + (uint32_t)(stg) * STAGE_BYTES; \
    size_t ko_ = (size_t)(itn) * 32; \
    _Pragma("unroll") \
    for (int q_ = 0; q_ < 12; ++q_) \
        asm volatile("cp.async.cg.shared.global [%0], [%1], 16;" \
                     :: "r"(db_ + dsto[q_]), "l"(srcp[q_] + ko_)); \
    asm volatile("cp.async.commit_group;"); \
} while (0)

__global__ void __launch_bounds__(256, 1) gemm_kernel() {
    extern __shared__ char smem[];
    const uint32_t sbase = (smem_u32(smem) + 127u) & ~127u;
    const int tid = threadIdx.x;
    const int bm = blockIdx.x >> 5, bn = blockIdx.x & 31;

    // precompute cp.async src pointers / swizzled dst offsets (12 chunks/thread)
    const float* srcp[12];
    uint32_t dsto[12];
#pragma unroll
    for (int q = 0; q < 12; ++q) {
        int ch = tid + (q << 8);
        int isB = ch >= 2048;
        int row = (isB ? ch - 2048 : ch) >> 3;
        int c = ch & 7;
        int pr = (((row & 7) << 1) & 7) | ((row & 7) >> 2);
        srcp[q] = (isB ? g_B + (size_t)(bn * 128 + row) * 4096
                       : g_A + (size_t)(bm * 256 + row) * 4096) + c * 4;
        dsto[q] = (uint32_t)((isB ? A_BYTES : 0) + row * 128 + ((c ^ pr) << 4));
    }

    const int wid = tid >> 5, lane = tid & 31;
    const int gid = lane >> 2, qd = lane & 3;
    const int wm = wid >> 1, wn = wid & 1;
    const int p = ((gid << 1) & 7) | (gid >> 2);

    float acc[4][8][4];
#pragma unroll
    for (int i = 0; i < 4; ++i)
#pragma unroll
        for (int j = 0; j < 8; ++j)
#pragma unroll
            for (int r = 0; r < 4; ++r) acc[i][j][r] = 0.0f;

    LOAD_STAGE(0, 0);
    LOAD_STAGE(1, 1);

    for (int it = 0; it < NIT; ++it) {
        if (it + 1 < NIT) asm volatile("cp.async.wait_group 1;");
        else              asm volatile("cp.async.wait_group 0;");
        __syncthreads();
        if (it + 2 < NIT) LOAD_STAGE((it + 2) % 3, it + 2);

        const uint32_t sA = sbase + (uint32_t)(it % 3) * STAGE_BYTES;
        const uint32_t sB = sA + A_BYTES;
#pragma unroll
        for (int ks = 0; ks < 4; ++ks) {
            const int chunk = ks * 2 + (qd >> 1);
            const uint32_t coff = (uint32_t)(((chunk ^ p) << 4) + ((qd & 1) << 3));
            uint32_t av[4][4];
#pragma unroll
            for (int i = 0; i < 4; ++i) {
                uint32_t r0 = sA + (uint32_t)((wm * 64 + i * 16 + gid) * 128) + coff;
                asm volatile("ld.shared.v2.b32 {%0,%1}, [%2];"
                             : "=r"(av[i][0]), "=r"(av[i][2]) : "r"(r0));
                asm volatile("ld.shared.v2.b32 {%0,%1}, [%2];"
                             : "=r"(av[i][1]), "=r"(av[i][3]) : "r"(r0 + 8 * 128));
            }
            uint32_t bv[8][2];
#pragma unroll
            for (int j = 0; j < 8; ++j) {
                uint32_t rb = sB + (uint32_t)((wn * 64 + j * 8 + gid) * 128) + coff;
                asm volatile("ld.shared.v2.b32 {%0,%1}, [%2];"
                             : "=r"(bv[j][0]), "=r"(bv[j][1]) : "r"(rb));
            }
#pragma unroll
            for (int i = 0; i < 4; ++i)
#pragma unroll
                for (int j = 0; j < 8; ++j)
                    asm volatile(
                        "mma.sync.aligned.m16n8k8.row.col.f32.tf32.tf32.f32 "
                        "{%0,%1,%2,%3}, {%4,%5,%6,%7}, {%8,%9}, {%0,%1,%2,%3};"
                        : "+f"(acc[i][j][0]), "+f"(acc[i][j][1]),
                          "+f"(acc[i][j][2]), "+f"(acc[i][j][3])
                        : "r"(av[i][0]), "r"(av[i][1]), "r"(av[i][2]), "r"(av[i][3]),
                          "r"(bv[j][0]), "r"(bv[j][1]));
        }
    }

    const size_t m0 = (size_t)bm * 256, n0 = (size_t)bn * 128;
#pragma unroll
    for (int i = 0; i < 4; ++i) {
        size_t row0 = m0 + wm * 64 + i * 16 + gid;
#pragma unroll
        for (int j = 0; j < 8; ++j) {
            size_t col = n0 + wn * 64 + j * 8 + qd * 2;
            *(float2*)&g_D[row0 * 4096 + col]       = make_float2(acc[i][j][0], acc[i][j][1]);
            *(float2*)&g_D[(row0 + 8) * 4096 + col] = make_float2(acc[i][j][2], acc[i][j][3]);
        }
    }
}

// ---------------- epilogue: gates + state update (+ mean term, biases) ----------------
__global__ void epilogue(const float* __restrict__ c_in,
                         const float* __restrict__ b_ii, const float* __restrict__ b_hi,
                         const float* __restrict__ b_if, const float* __restrict__ b_hf,
                         const float* __restrict__ b_ig, const float* __restrict__ b_hg,
                         const float* __restrict__ b_io, const float* __restrict__ b_ho,
                         float* __restrict__ out) {
    __shared__ float sP[32][33], sF[32][33], sO[32][33];
    const int tx = threadIdx.x, ty = threadIdx.y;
    const int n0 = blockIdx.x * 32, m0 = blockIdx.y * 32;
    const size_t G = (size_t)2048 * 4096;
#pragma unroll
    for (int r = 0; r < 4; ++r) {
        int ml = ty * 4 + r, m = m0 + ml, n = n0 + tx;
        size_t base = (size_t)m * 4096 + n;
        float s2 = 0.2f * g_S[n];
        float iv = sigmf(g_D[base]         + s2 + b_ii[m] + b_hi[m]);
        float fv = sigmf(g_D[base + G]     + s2 + b_if[m] + b_hf[m]);
        float gv = tanhf(g_D[base + 2 * G] + s2 + b_ig[m] + b_hg[m]);
        float ov = sigmf(g_D[base + 3 * G] + s2 + b_io[m] + b_ho[m]);
        sP[ml][tx] = iv * gv; sF[ml][tx] = fv; sO[ml][tx] = ov;
    }
    __syncthreads();
    float* out_c = out + (size_t)4096 * 2048;
#pragma unroll
    for (int r = 0; r < 4; ++r) {
        int nl = ty * 4 + r, n = n0 + nl, m = m0 + tx;
        float cv = c_in[(size_t)n * 2048 + m];
        float cn = sF[tx][nl] * cv + sP[tx][nl];
        float hn = sO[tx][nl] * tanhf(cn);
        out[(size_t)n * 2048 + m]   = hn;
        out_c[(size_t)n * 2048 + m] = cn;
    }
}

// ---------------- launcher ----------------
extern "C" void kernel_launch(void* const* d_in, const int* in_sizes, int n_in,
                              void* d_out, int out_size)
{
    (void)in_sizes; (void)n_in; (void)out_size;
    const float* x = (const float*)d_in[0];
    const float* h = (const float*)d_in[1];
    const float* c = (const float*)d_in[2];

    cudaFuncSetAttribute(gemm_kernel, cudaFuncAttributeMaxDynamicSharedMemorySize, SMEM_TOTAL);

    convA<<<32768, 256>>>((const float*)d_in[3], (const float*)d_in[4],
                          (const float*)d_in[5], (const float*)d_in[6],
                          (const float*)d_in[7], (const float*)d_in[8],
                          (const float*)d_in[9], (const float*)d_in[10]);
    convBh<<<8192, 256>>>(h);
    convBx<<<dim3(128, 64), dim3(32, 8)>>>(x);
    sumX<<<16, 256>>>(x);
    sumH<<<4096, 256>>>(h);

    gemm_kernel<<<1024, 256, SMEM_TOTAL>>>();

    epilogue<<<dim3(128, 64), dim3(32, 8)>>>(
        c,
        (const float*)d_in[11], (const float*)d_in[12],
        (const float*)d_in[13], (const float*)d_in[14],
        (const float*)d_in[15], (const float*)d_in[16],
        (const float*)d_in[17], (const float*)d_in[18],
        (float*)d_out);
}

// round 12
// speedup vs baseline: 1.8157x; 1.8157x over previous
#include <cuda_runtime.h>
#include <cuda_fp16.h>
#include <cstdint>

#define NIT 64                     // K=4096 in 64-wide slabs
#define A_BYTES 32768              // 256 rows x 128B (64 fp16 k)
#define B_BYTES 16384              // 128 rows x 128B
#define STAGE_BYTES (A_BYTES + B_BYTES)
#define SMEM_TOTAL (3*STAGE_BYTES + 256)
#define SG_STRIDE 130              // epilogue smem row stride (floats)

__device__ __half g_Ah[(size_t)8192 * 4096];  // [gate*2048+m][k], fp16, mean-removed
__device__ __half g_Bh[(size_t)4096 * 4096];  // [batch][k] = x^T || h, fp16
__device__ float  g_S[4096];                  // per-batch operand sums (fp32)

__device__ __forceinline__ uint32_t smem_u32(const void* p) {
    uint32_t a;
    asm("{ .reg .u64 t; cvta.to.shared.u64 t, %1; cvt.u32.u64 %0, t; }" : "=r"(a) : "l"(p));
    return a;
}
__device__ __forceinline__ float sigmf(float z) { return 1.0f / (1.0f + __expf(-z)); }

// ---------------- pre-pass ----------------
// A_cat: rows = gate*2048+m, cols k: k<2048 -> W_in, else W_h. Subtract 0.2 mean.
__global__ void convA(const float* __restrict__ a0, const float* __restrict__ a1,
                      const float* __restrict__ a2, const float* __restrict__ a3,
                      const float* __restrict__ h0, const float* __restrict__ h1,
                      const float* __restrict__ h2, const float* __restrict__ h3) {
    size_t i8 = (size_t)blockIdx.x * 256 + threadIdx.x;    // 4194304 threads, 8 halves each
    size_t flat = i8 << 3;
    int g = (int)(flat >> 23);
    int rem = (int)(flat & ((1u << 23) - 1));
    int m = rem >> 12, k = rem & 4095;
    const float* w = (k < 2048)
        ? ((g == 0) ? a0 : (g == 1) ? a1 : (g == 2) ? a2 : a3)
        : ((g == 0) ? h0 : (g == 1) ? h1 : (g == 2) ? h2 : h3);
    const float* src = w + (size_t)m * 2048 + (k & 2047);
    float4 v0 = *(const float4*)src;
    float4 v1 = *(const float4*)(src + 4);
    __half h8[8];
    h8[0] = __float2half_rn(v0.x - 0.2f); h8[1] = __float2half_rn(v0.y - 0.2f);
    h8[2] = __float2half_rn(v0.z - 0.2f); h8[3] = __float2half_rn(v0.w - 0.2f);
    h8[4] = __float2half_rn(v1.x - 0.2f); h8[5] = __float2half_rn(v1.y - 0.2f);
    h8[6] = __float2half_rn(v1.z - 0.2f); h8[7] = __float2half_rn(v1.w - 0.2f);
    *(uint4*)(g_Ah + flat) = *(uint4*)h8;
}

// h -> upper-K half of g_Bh; one block per batch row; also g_S[n] = sum(h row)
__global__ void convBh(const float* __restrict__ h) {
    __shared__ float red[256];
    const int n = blockIdx.x, t = threadIdx.x;
    const float* src = h + (size_t)n * 2048 + t * 8;
    float4 v0 = *(const float4*)src;
    float4 v1 = *(const float4*)(src + 4);
    __half h8[8];
    h8[0] = __float2half_rn(v0.x); h8[1] = __float2half_rn(v0.y);
    h8[2] = __float2half_rn(v0.z); h8[3] = __float2half_rn(v0.w);
    h8[4] = __float2half_rn(v1.x); h8[5] = __float2half_rn(v1.y);
    h8[6] = __float2half_rn(v1.z); h8[7] = __float2half_rn(v1.w);
    *(uint4*)(g_Bh + (size_t)n * 4096 + 2048 + t * 8) = *(uint4*)h8;
    red[t] = ((v0.x + v0.y) + (v0.z + v0.w)) + ((v1.x + v1.y) + (v1.z + v1.w));
    __syncthreads();
    for (int st = 128; st > 0; st >>= 1) {
        if (t < st) red[t] += red[t + st];
        __syncthreads();
    }
    if (t == 0) g_S[n] = red[0];     // written BEFORE convBx atomics (stream order)
}

// x [2048, 4096] -> transposed lower-K half of g_Bh; fold column sums into g_S
__global__ void convBx(const float* __restrict__ x) {
    __shared__ float t[32][33];
    const int n0 = blockIdx.x << 5, k0 = blockIdx.y << 5;
    const int tx = threadIdx.x, ty = threadIdx.y;
#pragma unroll
    for (int i = 0; i < 4; ++i)
        t[ty + i * 8][tx] = x[(size_t)(k0 + ty + i * 8) * 4096 + n0 + tx];
    __syncthreads();
#pragma unroll
    for (int i = 0; i < 4; ++i) {
        int n = ty + i * 8;
        g_Bh[(size_t)(n0 + n) * 4096 + k0 + tx] = __float2half_rn(t[tx][n]);
    }
    if (ty == 0) {                    // warp 0: per-n partial sums over this k-tile
        float s = 0.0f;
#pragma unroll
        for (int ky = 0; ky < 32; ++ky) s += t[ky][tx];
        atomicAdd(g_S + n0 + tx, s);
    }
}

// ---------------- fused fp16 GEMM + LSTM epilogue ----------------
// CTA: 64 m-rows x 128 n-cols x 4 gates. Warp tile: (4 gates x 16m) x 64n.
#define LOAD_STAGE(stg) do { \
    uint32_t db_ = sbase + (uint32_t)(stg) * STAGE_BYTES; \
    _Pragma("unroll") \
    for (int q_ = 0; q_ < 12; ++q_) { \
        asm volatile("cp.async.cg.shared.global [%0], [%1], 16;" \
                     :: "r"(db_ + dsto[q_]), "l"(srcp[q_])); \
        srcp[q_] += 64; \
    } \
    asm volatile("cp.async.commit_group;"); \
} while (0)

__global__ void __launch_bounds__(256, 1) gemm_fused(
    const float* __restrict__ c_in,
    const float* __restrict__ b_ii, const float* __restrict__ b_hi,
    const float* __restrict__ b_if, const float* __restrict__ b_hf,
    const float* __restrict__ b_ig, const float* __restrict__ b_hg,
    const float* __restrict__ b_io, const float* __restrict__ b_ho,
    float* __restrict__ out)
{
    extern __shared__ char smem[];
    const uint32_t sbase = (smem_u32(smem) + 127u) & ~127u;
    const int tid = threadIdx.x;
    const int bm = blockIdx.x >> 5, bn = blockIdx.x & 31;

    // cp.async: 12 x 16B chunks per thread (A 2048 + B 1024 chunks)
    const __half* srcp[12];
    uint32_t dsto[12];
#pragma unroll
    for (int q = 0; q < 12; ++q) {
        int ch = tid + (q << 8);
        if (ch < 2048) {
            int r = ch >> 3, c = ch & 7;
            int grow = (r >> 6) * 2048 + bm * 64 + (r & 63);   // gate panel gather
            srcp[q] = g_Ah + (size_t)grow * 4096 + c * 8;
            dsto[q] = (uint32_t)(r * 128 + ((c ^ (r & 7)) << 4));
        } else {
            int ch2 = ch - 2048;
            int r = ch2 >> 3, c = ch2 & 7;
            srcp[q] = g_Bh + (size_t)(bn * 128 + r) * 4096 + c * 8;
            dsto[q] = (uint32_t)(A_BYTES + r * 128 + ((c ^ (r & 7)) << 4));
        }
    }

    const int lane = tid & 31, wid = tid >> 5;
    const int wm = wid >> 1, wn = wid & 1;
    // ldmatrix lane geometry
    const int arow_l = wm * 16 + ((lane >> 3) & 1) * 8 + (lane & 7);
    const int akch_l = lane >> 4;                    // k-chunk (0/1) within kstep
    const int brow_l = wn * 64 + ((lane >> 4) & 1) * 8 + (lane & 7);
    const int bkch_l = (lane >> 3) & 1;

    float acc[4][8][4];
#pragma unroll
    for (int i = 0; i < 4; ++i)
#pragma unroll
        for (int j = 0; j < 8; ++j)
#pragma unroll
            for (int r = 0; r < 4; ++r) acc[i][j][r] = 0.0f;

    LOAD_STAGE(0);
    LOAD_STAGE(1);

    for (int it = 0; it < NIT; ++it) {
        if (it + 1 < NIT) asm volatile("cp.async.wait_group 1;");
        else              asm volatile("cp.async.wait_group 0;");
        __syncthreads();
        if (it + 2 < NIT) LOAD_STAGE((it + 2) % 3);

        const uint32_t sA = sbase + (uint32_t)(it % 3) * STAGE_BYTES;
        const uint32_t sB = sA + A_BYTES;
#pragma unroll
        for (int ks = 0; ks < 4; ++ks) {             // 4 x K=16
            uint32_t av[4][4], bv[4][4];
#pragma unroll
            for (int i = 0; i < 4; ++i) {            // i = gate (m block i*64)
                int row = i * 64 + arow_l;
                int chunk = ks * 2 + akch_l;
                uint32_t ad = sA + (uint32_t)(row * 128 + ((chunk ^ (row & 7)) << 4));
                asm volatile("ldmatrix.sync.aligned.m8n8.x4.shared.b16 {%0,%1,%2,%3}, [%4];"
                             : "=r"(av[i][0]), "=r"(av[i][1]), "=r"(av[i][2]), "=r"(av[i][3])
                             : "r"(ad));
            }
#pragma unroll
            for (int j2 = 0; j2 < 4; ++j2) {         // 2 n-octets x 2 k-chunks
                int row = brow_l + j2 * 16;
                int chunk = ks * 2 + bkch_l;
                uint32_t bd = sB + (uint32_t)(row * 128 + ((chunk ^ (row & 7)) << 4));
                asm volatile("ldmatrix.sync.aligned.m8n8.x4.shared.b16 {%0,%1,%2,%3}, [%4];"
                             : "=r"(bv[j2][0]), "=r"(bv[j2][1]), "=r"(bv[j2][2]), "=r"(bv[j2][3])
                             : "r"(bd));
            }
#pragma unroll
            for (int i = 0; i < 4; ++i)
#pragma unroll
                for (int j = 0; j < 8; ++j)
                    asm volatile(
                        "mma.sync.aligned.m16n8k16.row.col.f32.f16.f16.f32 "
                        "{%0,%1,%2,%3}, {%4,%5,%6,%7}, {%8,%9}, {%0,%1,%2,%3};"
                        : "+f"(acc[i][j][0]), "+f"(acc[i][j][1]),
                          "+f"(acc[i][j][2]), "+f"(acc[i][j][3])
                        : "r"(av[i][0]), "r"(av[i][1]), "r"(av[i][2]), "r"(av[i][3]),
                          "r"(bv[j >> 1][(j & 1) * 2]), "r"(bv[j >> 1][(j & 1) * 2 + 1]));
        }
    }
    __syncthreads();

    // ---- stage gates to smem [gate][64 m][128 n] (stride SG_STRIDE) ----
    float* sG = (float*)smem;
    {
        const int row = wm * 16 + (lane >> 2);
        const int col = wn * 64 + (lane & 3) * 2;
#pragma unroll
        for (int i = 0; i < 4; ++i)
#pragma unroll
            for (int j = 0; j < 8; ++j) {
                float* p = sG + (size_t)i * 64 * SG_STRIDE + row * SG_STRIDE + col + j * 8;
                *(float2*)p                     = make_float2(acc[i][j][0], acc[i][j][1]);
                *(float2*)(p + 8 * SG_STRIDE)   = make_float2(acc[i][j][2], acc[i][j][3]);
            }
    }
    __syncthreads();

    // ---- LSTM epilogue, coalesced along m ----
    const int m_l = tid & 63, nq = tid >> 6;
    const int m_g = bm * 64 + m_l;
    const float bsi = b_ii[m_g] + b_hi[m_g];
    const float bsf = b_if[m_g] + b_hf[m_g];
    const float bsg = b_ig[m_g] + b_hg[m_g];
    const float bso = b_io[m_g] + b_ho[m_g];
    float* out_c = out + (size_t)4096 * 2048;
    const float* row0 = sG + m_l * SG_STRIDE;
#pragma unroll 4
    for (int loop = 0; loop < 32; ++loop) {
        const int n_l = loop * 4 + nq;
        const int n_g = bn * 128 + n_l;
        const float s2 = 0.2f * g_S[n_g];
        float iv = sigmf(row0[0 * 64 * SG_STRIDE + n_l] + s2 + bsi);
        float fv = sigmf(row0[1 * 64 * SG_STRIDE + n_l] + s2 + bsf);
        float gv = tanhf(row0[2 * 64 * SG_STRIDE + n_l] + s2 + bsg);
        float ov = sigmf(row0[3 * 64 * SG_STRIDE + n_l] + s2 + bso);
        float cv = c_in[(size_t)n_g * 2048 + m_g];
        float cn = fv * cv + iv * gv;
        out_c[(size_t)n_g * 2048 + m_g] = cn;
        out[(size_t)n_g * 2048 + m_g]   = ov * tanhf(cn);
    }
}

// ---------------- launcher ----------------
extern "C" void kernel_launch(void* const* d_in, const int* in_sizes, int n_in,
                              void* d_out, int out_size)
{
    (void)in_sizes; (void)n_in; (void)out_size;
    const float* x = (const float*)d_in[0];
    const float* h = (const float*)d_in[1];
    const float* c = (const float*)d_in[2];

    cudaFuncSetAttribute(gemm_fused, cudaFuncAttributeMaxDynamicSharedMemorySize, SMEM_TOTAL);

    convA<<<16384, 256>>>((const float*)d_in[3], (const float*)d_in[4],
                          (const float*)d_in[5], (const float*)d_in[6],
                          (const float*)d_in[7], (const float*)d_in[8],
                          (const float*)d_in[9], (const float*)d_in[10]);
    convBh<<<4096, 256>>>(h);                 // writes g_S (must precede convBx)
    convBx<<<dim3(128, 64), dim3(32, 8)>>>(x); // atomicAdds into g_S

    gemm_fused<<<1024, 256, SMEM_TOTAL>>>(
        c,
        (const float*)d_in[11], (const float*)d_in[12],
        (const float*)d_in[13], (const float*)d_in[14],
        (const float*)d_in[15], (const float*)d_in[16],
        (const float*)d_in[17], (const float*)d_in[18],
        (float*)d_out);
}

// round 13
// speedup vs baseline: 1.8502x; 1.0190x over previous
#include <cuda_runtime.h>
#include <cuda_fp16.h>
#include <cstdint>

#define NIT 64                     // K=4096 in 64-wide slabs
#define A_BYTES 32768              // 256 rows x 128B (64 fp16 k)
#define B_BYTES 16384              // 128 rows x 128B
#define STAGE_BYTES (A_BYTES + B_BYTES)
#define SMEM_TOTAL (3*STAGE_BYTES + 256)
#define SG_STRIDE 130              // epilogue smem row stride (floats)

// g_Ah rows INTERLEAVED: row' = m*4 + gate  (CTA A-tile = contiguous 256 rows)
__device__ __half g_Ah[(size_t)8192 * 4096];
__device__ __half g_Bh[(size_t)4096 * 4096];  // [batch][k] = x^T || h, fp16
__device__ float  g_S[4096];                  // per-batch operand sums (fp32)

__device__ __forceinline__ uint32_t smem_u32(const void* p) {
    uint32_t a;
    asm("{ .reg .u64 t; cvta.to.shared.u64 t, %1; cvt.u32.u64 %0, t; }" : "=r"(a) : "l"(p));
    return a;
}
__device__ __forceinline__ float sigmf(float z) { return 1.0f / (1.0f + __expf(-z)); }

// ---------------- pre-pass ----------------
__global__ void convA(const float* __restrict__ a0, const float* __restrict__ a1,
                      const float* __restrict__ a2, const float* __restrict__ a3,
                      const float* __restrict__ h0, const float* __restrict__ h1,
                      const float* __restrict__ h2, const float* __restrict__ h3) {
    size_t i8 = (size_t)blockIdx.x * 256 + threadIdx.x;
    size_t flat = i8 << 3;
    int rp = (int)(flat >> 12);          // interleaved row = m*4+g
    int k  = (int)(flat & 4095);
    int m = rp >> 2, g = rp & 3;
    const float* w = (k < 2048)
        ? ((g == 0) ? a0 : (g == 1) ? a1 : (g == 2) ? a2 : a3)
        : ((g == 0) ? h0 : (g == 1) ? h1 : (g == 2) ? h2 : h3);
    const float* src = w + (size_t)m * 2048 + (k & 2047);
    float4 v0 = *(const float4*)src;
    float4 v1 = *(const float4*)(src + 4);
    __half h8[8];
    h8[0] = __float2half_rn(v0.x - 0.2f); h8[1] = __float2half_rn(v0.y - 0.2f);
    h8[2] = __float2half_rn(v0.z - 0.2f); h8[3] = __float2half_rn(v0.w - 0.2f);
    h8[4] = __float2half_rn(v1.x - 0.2f); h8[5] = __float2half_rn(v1.y - 0.2f);
    h8[6] = __float2half_rn(v1.z - 0.2f); h8[7] = __float2half_rn(v1.w - 0.2f);
    *(uint4*)(g_Ah + flat) = *(uint4*)h8;
}

__global__ void convBh(const float* __restrict__ h) {
    __shared__ float red[256];
    const int n = blockIdx.x, t = threadIdx.x;
    const float* src = h + (size_t)n * 2048 + t * 8;
    float4 v0 = *(const float4*)src;
    float4 v1 = *(const float4*)(src + 4);
    __half h8[8];
    h8[0] = __float2half_rn(v0.x); h8[1] = __float2half_rn(v0.y);
    h8[2] = __float2half_rn(v0.z); h8[3] = __float2half_rn(v0.w);
    h8[4] = __float2half_rn(v1.x); h8[5] = __float2half_rn(v1.y);
    h8[6] = __float2half_rn(v1.z); h8[7] = __float2half_rn(v1.w);
    *(uint4*)(g_Bh + (size_t)n * 4096 + 2048 + t * 8) = *(uint4*)h8;
    red[t] = ((v0.x + v0.y) + (v0.z + v0.w)) + ((v1.x + v1.y) + (v1.z + v1.w));
    __syncthreads();
    for (int st = 128; st > 0; st >>= 1) {
        if (t < st) red[t] += red[t + st];
        __syncthreads();
    }
    if (t == 0) g_S[n] = red[0];
}

__global__ void convBx(const float* __restrict__ x) {
    __shared__ float t[32][33];
    const int n0 = blockIdx.x << 5, k0 = blockIdx.y << 5;
    const int tx = threadIdx.x, ty = threadIdx.y;
#pragma unroll
    for (int i = 0; i < 4; ++i)
        t[ty + i * 8][tx] = x[(size_t)(k0 + ty + i * 8) * 4096 + n0 + tx];
    __syncthreads();
#pragma unroll
    for (int i = 0; i < 4; ++i) {
        int n = ty + i * 8;
        g_Bh[(size_t)(n0 + n) * 4096 + k0 + tx] = __float2half_rn(t[tx][n]);
    }
    if (ty == 0) {
        float s = 0.0f;
#pragma unroll
        for (int ky = 0; ky < 32; ++ky) s += t[ky][tx];
        atomicAdd(g_S + n0 + tx, s);
    }
}

// ---------------- fused fp16 GEMM + LSTM epilogue ----------------
#define LOAD_STAGE(stg) do { \
    uint32_t da_ = sbase + (uint32_t)(stg) * STAGE_BYTES + dst0; \
    const __half* pa_ = srcA; \
    _Pragma("unroll") \
    for (int q_ = 0; q_ < 8; ++q_) { \
        asm volatile("cp.async.cg.shared.global [%0], [%1], 16;" :: "r"(da_), "l"(pa_)); \
        da_ += 4096; pa_ += (size_t)32 * 4096; \
    } \
    uint32_t db_ = sbase + (uint32_t)(stg) * STAGE_BYTES + A_BYTES + dst0; \
    const __half* pb_ = srcB; \
    _Pragma("unroll") \
    for (int q_ = 0; q_ < 4; ++q_) { \
        asm volatile("cp.async.cg.shared.global [%0], [%1], 16;" :: "r"(db_), "l"(pb_)); \
        db_ += 4096; pb_ += (size_t)32 * 4096; \
    } \
    asm volatile("cp.async.commit_group;"); \
    srcA += 64; srcB += 64; \
} while (0)

#define LDFRAG(buf, ks) do { \
    const int chA_ = (ks) * 2 + akch_l; \
    _Pragma("unroll") \
    for (int i_ = 0; i_ < 4; ++i_) { \
        int row_ = i_ * 64 + arow_l; \
        uint32_t ad_ = sA + (uint32_t)(row_ * 128 + ((chA_ ^ (row_ & 7)) << 4)); \
        asm volatile("ldmatrix.sync.aligned.m8n8.x4.shared.b16 {%0,%1,%2,%3}, [%4];" \
            : "=r"(av[buf][i_][0]), "=r"(av[buf][i_][1]), \
              "=r"(av[buf][i_][2]), "=r"(av[buf][i_][3]) : "r"(ad_)); \
    } \
    const int chB_ = (ks) * 2 + bkch_l; \
    _Pragma("unroll") \
    for (int j_ = 0; j_ < 4; ++j_) { \
        int row_ = brow_l + j_ * 16; \
        uint32_t bd_ = sB + (uint32_t)(row_ * 128 + ((chB_ ^ (row_ & 7)) << 4)); \
        asm volatile("ldmatrix.sync.aligned.m8n8.x4.shared.b16 {%0,%1,%2,%3}, [%4];" \
            : "=r"(bv[buf][j_][0]), "=r"(bv[buf][j_][1]), \
              "=r"(bv[buf][j_][2]), "=r"(bv[buf][j_][3]) : "r"(bd_)); \
    } \
} while (0)

#define DO_MMAS(buf) do { \
    _Pragma("unroll") \
    for (int i_ = 0; i_ < 4; ++i_) \
    _Pragma("unroll") \
    for (int j_ = 0; j_ < 8; ++j_) \
        asm volatile( \
            "mma.sync.aligned.m16n8k16.row.col.f32.f16.f16.f32 " \
            "{%0,%1,%2,%3}, {%4,%5,%6,%7}, {%8,%9}, {%0,%1,%2,%3};" \
            : "+f"(acc[i_][j_][0]), "+f"(acc[i_][j_][1]), \
              "+f"(acc[i_][j_][2]), "+f"(acc[i_][j_][3]) \
            : "r"(av[buf][i_][0]), "r"(av[buf][i_][1]), \
              "r"(av[buf][i_][2]), "r"(av[buf][i_][3]), \
              "r"(bv[buf][j_ >> 1][(j_ & 1) * 2]), \
              "r"(bv[buf][j_ >> 1][(j_ & 1) * 2 + 1])); \
} while (0)

__global__ void __launch_bounds__(256, 1) gemm_fused(
    const float* __restrict__ c_in,
    const float* __restrict__ b_ii, const float* __restrict__ b_hi,
    const float* __restrict__ b_if, const float* __restrict__ b_hf,
    const float* __restrict__ b_ig, const float* __restrict__ b_hg,
    const float* __restrict__ b_io, const float* __restrict__ b_ho,
    float* __restrict__ out)
{
    extern __shared__ char smem[];
    const uint32_t sbase = (smem_u32(smem) + 127u) & ~127u;
    const int tid = threadIdx.x;
    const int bm = blockIdx.x >> 5, bn = blockIdx.x & 31;

    // cp.async bases (constant strides thanks to interleaved A rows)
    const int r0 = tid >> 3, c0 = tid & 7;
    const uint32_t dst0 = (uint32_t)(r0 * 128 + ((c0 ^ (r0 & 7)) << 4));
    const __half* srcA = g_Ah + (size_t)(bm * 256 + r0) * 4096 + c0 * 8;
    const __half* srcB = g_Bh + (size_t)(bn * 128 + r0) * 4096 + c0 * 8;

    const int lane = tid & 31, wid = tid >> 5;
    const int wm = wid >> 1, wn = wid & 1;
    const int arow_l = wm * 16 + ((lane >> 3) & 1) * 8 + (lane & 7);
    const int akch_l = lane >> 4;
    const int brow_l = wn * 64 + ((lane >> 4) & 1) * 8 + (lane & 7);
    const int bkch_l = (lane >> 3) & 1;

    float acc[4][8][4];
#pragma unroll
    for (int i = 0; i < 4; ++i)
#pragma unroll
        for (int j = 0; j < 8; ++j)
#pragma unroll
            for (int r = 0; r < 4; ++r) acc[i][j][r] = 0.0f;

    uint32_t av[2][4][4], bv[2][4][4];

    LOAD_STAGE(0);
    LOAD_STAGE(1);

    for (int it = 0; it < NIT; ++it) {
        if (it + 1 < NIT) asm volatile("cp.async.wait_group 1;");
        else              asm volatile("cp.async.wait_group 0;");
        __syncthreads();

        const uint32_t sA = sbase + (uint32_t)(it % 3) * STAGE_BYTES;
        const uint32_t sB = sA + A_BYTES;

        LDFRAG(0, 0);                    // start fragments before cp.async issue
        if (it + 2 < NIT) LOAD_STAGE((it + 2) % 3);

        LDFRAG(1, 1);  DO_MMAS(0);
        LDFRAG(0, 2);  DO_MMAS(1);
        LDFRAG(1, 3);  DO_MMAS(0);
                       DO_MMAS(1);
    }
    __syncthreads();

    // ---- stage gates to smem: row' = m*4+gate -> sG[gate][64 m][128 n] ----
    float* sG = (float*)smem;
    {
        const int rbase = wm * 16 + (lane >> 2);
        const int col = wn * 64 + (lane & 3) * 2;
#pragma unroll
        for (int i = 0; i < 4; ++i)
#pragma unroll
            for (int rr = 0; rr < 2; ++rr) {
                int row = i * 64 + rbase + rr * 8;
                float* p = sG + (size_t)(row & 3) * 64 * SG_STRIDE
                              + (row >> 2) * SG_STRIDE + col;
#pragma unroll
                for (int j = 0; j < 8; ++j)
                    *(float2*)(p + j * 8) =
                        make_float2(acc[i][j][rr * 2], acc[i][j][rr * 2 + 1]);
            }
    }
    __syncthreads();

    // ---- LSTM epilogue, coalesced along m ----
    const int m_l = tid & 63, nq = tid >> 6;
    const int m_g = bm * 64 + m_l;
    const float bsi = b_ii[m_g] + b_hi[m_g];
    const float bsf = b_if[m_g] + b_hf[m_g];
    const float bsg = b_ig[m_g] + b_hg[m_g];
    const float bso = b_io[m_g] + b_ho[m_g];
    float* out_c = out + (size_t)4096 * 2048;
    const float* row0 = sG + m_l * SG_STRIDE;
#pragma unroll 4
    for (int loop = 0; loop < 32; ++loop) {
        const int n_l = loop * 4 + nq;
        const int n_g = bn * 128 + n_l;
        const float s2 = 0.2f * g_S[n_g];
        float iv = sigmf(row0[0 * 64 * SG_STRIDE + n_l] + s2 + bsi);
        float fv = sigmf(row0[1 * 64 * SG_STRIDE + n_l] + s2 + bsf);
        float gv = tanhf(row0[2 * 64 * SG_STRIDE + n_l] + s2 + bsg);
        float ov = sigmf(row0[3 * 64 * SG_STRIDE + n_l] + s2 + bso);
        float cv = c_in[(size_t)n_g * 2048 + m_g];
        float cn = fv * cv + iv * gv;
        out_c[(size_t)n_g * 2048 + m_g] = cn;
        out[(size_t)n_g * 2048 + m_g]   = ov * tanhf(cn);
    }
}

// ---------------- launcher ----------------
extern "C" void kernel_launch(void* const* d_in, const int* in_sizes, int n_in,
                              void* d_out, int out_size)
{
    (void)in_sizes; (void)n_in; (void)out_size;
    const float* x = (const float*)d_in[0];
    const float* h = (const float*)d_in[1];
    const float* c = (const float*)d_in[2];

    cudaFuncSetAttribute(gemm_fused, cudaFuncAttributeMaxDynamicSharedMemorySize, SMEM_TOTAL);

    convA<<<16384, 256>>>((const float*)d_in[3], (const float*)d_in[4],
                          (const float*)d_in[5], (const float*)d_in[6],
                          (const float*)d_in[7], (const float*)d_in[8],
                          (const float*)d_in[9], (const float*)d_in[10]);
    convBh<<<4096, 256>>>(h);
    convBx<<<dim3(128, 64), dim3(32, 8)>>>(x);

    gemm_fused<<<1024, 256, SMEM_TOTAL>>>(
        c,
        (const float*)d_in[11], (const float*)d_in[12],
        (const float*)d_in[13], (const float*)d_in[14],
        (const float*)d_in[15], (const float*)d_in[16],
        (const float*)d_in[17], (const float*)d_in[18],
        (float*)d_out);
}

// round 14
// speedup vs baseline: 2.1560x; 1.1653x over previous
#include <cuda_runtime.h>
#include <cuda_fp16.h>
#include <cstdint>

#define NIT 64                     // K=4096 in 64-wide slabs
#define A_BYTES 16384              // 128 rows x 128B
#define B_BYTES 16384              // 128 rows x 128B
#define STAGE_BYTES (A_BYTES + B_BYTES)
#define SMEM_TOTAL (3*STAGE_BYTES + 256)   // 98560/CTA -> 2 CTAs/SM
#define SG_STRIDE 130              // epilogue smem row stride (floats)

// g_Ah rows INTERLEAVED: row' = m*4 + gate  (CTA A-tile = contiguous 128 rows)
__device__ __half g_Ah[(size_t)8192 * 4096];
__device__ __half g_Bh[(size_t)4096 * 4096];  // [batch][k] = x^T || h, fp16
__device__ float  g_S[4096];                  // per-batch operand sums (fp32)

__device__ __forceinline__ uint32_t smem_u32(const void* p) {
    uint32_t a;
    asm("{ .reg .u64 t; cvta.to.shared.u64 t, %1; cvt.u32.u64 %0, t; }" : "=r"(a) : "l"(p));
    return a;
}
__device__ __forceinline__ float sigmf(float z) { return 1.0f / (1.0f + __expf(-z)); }

// ---------------- pre-pass ----------------
__global__ void convA(const float* __restrict__ a0, const float* __restrict__ a1,
                      const float* __restrict__ a2, const float* __restrict__ a3,
                      const float* __restrict__ h0, const float* __restrict__ h1,
                      const float* __restrict__ h2, const float* __restrict__ h3) {
    size_t i8 = (size_t)blockIdx.x * 256 + threadIdx.x;
    size_t flat = i8 << 3;
    int rp = (int)(flat >> 12);          // interleaved row = m*4+g
    int k  = (int)(flat & 4095);
    int m = rp >> 2, g = rp & 3;
    const float* w = (k < 2048)
        ? ((g == 0) ? a0 : (g == 1) ? a1 : (g == 2) ? a2 : a3)
        : ((g == 0) ? h0 : (g == 1) ? h1 : (g == 2) ? h2 : h3);
    const float* src = w + (size_t)m * 2048 + (k & 2047);
    float4 v0 = *(const float4*)src;
    float4 v1 = *(const float4*)(src + 4);
    __half h8[8];
    h8[0] = __float2half_rn(v0.x - 0.2f); h8[1] = __float2half_rn(v0.y - 0.2f);
    h8[2] = __float2half_rn(v0.z - 0.2f); h8[3] = __float2half_rn(v0.w - 0.2f);
    h8[4] = __float2half_rn(v1.x - 0.2f); h8[5] = __float2half_rn(v1.y - 0.2f);
    h8[6] = __float2half_rn(v1.z - 0.2f); h8[7] = __float2half_rn(v1.w - 0.2f);
    *(uint4*)(g_Ah + flat) = *(uint4*)h8;
}

__global__ void convBh(const float* __restrict__ h) {
    __shared__ float red[256];
    const int n = blockIdx.x, t = threadIdx.x;
    const float* src = h + (size_t)n * 2048 + t * 8;
    float4 v0 = *(const float4*)src;
    float4 v1 = *(const float4*)(src + 4);
    __half h8[8];
    h8[0] = __float2half_rn(v0.x); h8[1] = __float2half_rn(v0.y);
    h8[2] = __float2half_rn(v0.z); h8[3] = __float2half_rn(v0.w);
    h8[4] = __float2half_rn(v1.x); h8[5] = __float2half_rn(v1.y);
    h8[6] = __float2half_rn(v1.z); h8[7] = __float2half_rn(v1.w);
    *(uint4*)(g_Bh + (size_t)n * 4096 + 2048 + t * 8) = *(uint4*)h8;
    red[t] = ((v0.x + v0.y) + (v0.z + v0.w)) + ((v1.x + v1.y) + (v1.z + v1.w));
    __syncthreads();
    for (int st = 128; st > 0; st >>= 1) {
        if (t < st) red[t] += red[t + st];
        __syncthreads();
    }
    if (t == 0) g_S[n] = red[0];
}

__global__ void convBx(const float* __restrict__ x) {
    __shared__ float t[32][33];
    const int n0 = blockIdx.x << 5, k0 = blockIdx.y << 5;
    const int tx = threadIdx.x, ty = threadIdx.y;
#pragma unroll
    for (int i = 0; i < 4; ++i)
        t[ty + i * 8][tx] = x[(size_t)(k0 + ty + i * 8) * 4096 + n0 + tx];
    __syncthreads();
#pragma unroll
    for (int i = 0; i < 4; ++i) {
        int n = ty + i * 8;
        g_Bh[(size_t)(n0 + n) * 4096 + k0 + tx] = __float2half_rn(t[tx][n]);
    }
    if (ty == 0) {
        float s = 0.0f;
#pragma unroll
        for (int ky = 0; ky < 32; ++ky) s += t[ky][tx];
        atomicAdd(g_S + n0 + tx, s);
    }
}

// ---------------- fused fp16 GEMM + LSTM epilogue ----------------
// CTA: 128 threads (4 warps), tile = 128 A-rows x 128 n. Warp tile 64x64.
#define LOAD_STAGE(stg) do { \
    uint32_t da_ = sbase + (uint32_t)(stg) * STAGE_BYTES + dst0; \
    const __half* pa_ = srcA; \
    _Pragma("unroll") \
    for (int q_ = 0; q_ < 8; ++q_) { \
        asm volatile("cp.async.cg.shared.global [%0], [%1], 16;" :: "r"(da_), "l"(pa_)); \
        da_ += 2048; pa_ += (size_t)16 * 4096; \
    } \
    uint32_t db_ = sbase + (uint32_t)(stg) * STAGE_BYTES + A_BYTES + dst0; \
    const __half* pb_ = srcB; \
    _Pragma("unroll") \
    for (int q_ = 0; q_ < 8; ++q_) { \
        asm volatile("cp.async.cg.shared.global [%0], [%1], 16;" :: "r"(db_), "l"(pb_)); \
        db_ += 2048; pb_ += (size_t)16 * 4096; \
    } \
    asm volatile("cp.async.commit_group;"); \
    srcA += 64; srcB += 64; \
} while (0)

#define LDFRAG(buf, ks) do { \
    const int chA_ = (ks) * 2 + akch_l; \
    _Pragma("unroll") \
    for (int i_ = 0; i_ < 4; ++i_) { \
        int row_ = i_ * 16 + arow_l; \
        uint32_t ad_ = sA + (uint32_t)(row_ * 128 + ((chA_ ^ (row_ & 7)) << 4)); \
        asm volatile("ldmatrix.sync.aligned.m8n8.x4.shared.b16 {%0,%1,%2,%3}, [%4];" \
            : "=r"(av[buf][i_][0]), "=r"(av[buf][i_][1]), \
              "=r"(av[buf][i_][2]), "=r"(av[buf][i_][3]) : "r"(ad_)); \
    } \
    const int chB_ = (ks) * 2 + bkch_l; \
    _Pragma("unroll") \
    for (int j_ = 0; j_ < 4; ++j_) { \
        int row_ = brow_l + j_ * 16; \
        uint32_t bd_ = sB + (uint32_t)(row_ * 128 + ((chB_ ^ (row_ & 7)) << 4)); \
        asm volatile("ldmatrix.sync.aligned.m8n8.x4.shared.b16 {%0,%1,%2,%3}, [%4];" \
            : "=r"(bv[buf][j_][0]), "=r"(bv[buf][j_][1]), \
              "=r"(bv[buf][j_][2]), "=r"(bv[buf][j_][3]) : "r"(bd_)); \
    } \
} while (0)

#define DO_MMAS(buf) do { \
    _Pragma("unroll") \
    for (int i_ = 0; i_ < 4; ++i_) \
    _Pragma("unroll") \
    for (int j_ = 0; j_ < 8; ++j_) \
        asm volatile( \
            "mma.sync.aligned.m16n8k16.row.col.f32.f16.f16.f32 " \
            "{%0,%1,%2,%3}, {%4,%5,%6,%7}, {%8,%9}, {%0,%1,%2,%3};" \
            : "+f"(acc[i_][j_][0]), "+f"(acc[i_][j_][1]), \
              "+f"(acc[i_][j_][2]), "+f"(acc[i_][j_][3]) \
            : "r"(av[buf][i_][0]), "r"(av[buf][i_][1]), \
              "r"(av[buf][i_][2]), "r"(av[buf][i_][3]), \
              "r"(bv[buf][j_ >> 1][(j_ & 1) * 2]), \
              "r"(bv[buf][j_ >> 1][(j_ & 1) * 2 + 1])); \
} while (0)

__global__ void __launch_bounds__(128, 2) gemm_fused(
    const float* __restrict__ c_in,
    const float* __restrict__ b_ii, const float* __restrict__ b_hi,
    const float* __restrict__ b_if, const float* __restrict__ b_hf,
    const float* __restrict__ b_ig, const float* __restrict__ b_hg,
    const float* __restrict__ b_io, const float* __restrict__ b_ho,
    float* __restrict__ out)
{
    extern __shared__ char smem[];
    const uint32_t sbase = (smem_u32(smem) + 127u) & ~127u;
    const int tid = threadIdx.x;
    const int bm = blockIdx.x >> 5, bn = blockIdx.x & 31;   // 64 x 32 tiles

    // cp.async bases: 16 rows per pass, 8 passes per operand
    const int r0 = tid >> 3, c0 = tid & 7;
    const uint32_t dst0 = (uint32_t)(r0 * 128 + ((c0 ^ (r0 & 7)) << 4));
    const __half* srcA = g_Ah + (size_t)(bm * 128 + r0) * 4096 + c0 * 8;
    const __half* srcB = g_Bh + (size_t)(bn * 128 + r0) * 4096 + c0 * 8;

    const int lane = tid & 31, wid = tid >> 5;
    const int wm = wid >> 1, wn = wid & 1;
    const int arow_l = wm * 64 + ((lane >> 3) & 1) * 8 + (lane & 7);
    const int akch_l = lane >> 4;
    const int brow_l = wn * 64 + ((lane >> 4) & 1) * 8 + (lane & 7);
    const int bkch_l = (lane >> 3) & 1;

    float acc[4][8][4];
#pragma unroll
    for (int i = 0; i < 4; ++i)
#pragma unroll
        for (int j = 0; j < 8; ++j)
#pragma unroll
            for (int r = 0; r < 4; ++r) acc[i][j][r] = 0.0f;

    uint32_t av[2][4][4], bv[2][4][4];

    LOAD_STAGE(0);
    LOAD_STAGE(1);

    for (int it = 0; it < NIT; ++it) {
        if (it + 1 < NIT) asm volatile("cp.async.wait_group 1;");
        else              asm volatile("cp.async.wait_group 0;");
        __syncthreads();

        const uint32_t sA = sbase + (uint32_t)(it % 3) * STAGE_BYTES;
        const uint32_t sB = sA + A_BYTES;

        LDFRAG(0, 0);
        if (it + 2 < NIT) LOAD_STAGE((it + 2) % 3);

        LDFRAG(1, 1);  DO_MMAS(0);
        LDFRAG(0, 2);  DO_MMAS(1);
        LDFRAG(1, 3);  DO_MMAS(0);
                       DO_MMAS(1);
    }
    __syncthreads();

    // ---- stage gates: local A-row = m*4+gate -> sG[gate][32 m][128 n] ----
    float* sG = (float*)smem;
    {
        const int rbase = wm * 64 + (lane >> 2);
        const int col = wn * 64 + (lane & 3) * 2;
#pragma unroll
        for (int i = 0; i < 4; ++i)
#pragma unroll
            for (int rr = 0; rr < 2; ++rr) {
                int row = rbase + i * 16 + rr * 8;
                float* p = sG + (size_t)(row & 3) * 32 * SG_STRIDE
                              + (row >> 2) * SG_STRIDE + col;
#pragma unroll
                for (int j = 0; j < 8; ++j)
                    *(float2*)(p + j * 8) =
                        make_float2(acc[i][j][rr * 2], acc[i][j][rr * 2 + 1]);
            }
    }
    __syncthreads();

    // ---- LSTM epilogue, coalesced along m (warp = 32 consecutive m) ----
    const int m_l = tid & 31, nq = tid >> 5;
    const int m_g = bm * 32 + m_l;
    const float bsi = b_ii[m_g] + b_hi[m_g];
    const float bsf = b_if[m_g] + b_hf[m_g];
    const float bsg = b_ig[m_g] + b_hg[m_g];
    const float bso = b_io[m_g] + b_ho[m_g];
    float* out_c = out + (size_t)4096 * 2048;
    const float* row0 = sG + m_l * SG_STRIDE;
#pragma unroll 4
    for (int loop = 0; loop < 32; ++loop) {
        const int n_l = loop * 4 + nq;
        const int n_g = bn * 128 + n_l;
        const float s2 = 0.2f * g_S[n_g];
        float iv = sigmf(row0[0 * 32 * SG_STRIDE + n_l] + s2 + bsi);
        float fv = sigmf(row0[1 * 32 * SG_STRIDE + n_l] + s2 + bsf);
        float gv = tanhf(row0[2 * 32 * SG_STRIDE + n_l] + s2 + bsg);
        float ov = sigmf(row0[3 * 32 * SG_STRIDE + n_l] + s2 + bso);
        float cv = c_in[(size_t)n_g * 2048 + m_g];
        float cn = fv * cv + iv * gv;
        out_c[(size_t)n_g * 2048 + m_g] = cn;
        out[(size_t)n_g * 2048 + m_g]   = ov * tanhf(cn);
    }
}

// ---------------- launcher ----------------
extern "C" void kernel_launch(void* const* d_in, const int* in_sizes, int n_in,
                              void* d_out, int out_size)
{
    (void)in_sizes; (void)n_in; (void)out_size;
    const float* x = (const float*)d_in[0];
    const float* h = (const float*)d_in[1];
    const float* c = (const float*)d_in[2];

    cudaFuncSetAttribute(gemm_fused, cudaFuncAttributeMaxDynamicSharedMemorySize, SMEM_TOTAL);

    convA<<<16384, 256>>>((const float*)d_in[3], (const float*)d_in[4],
                          (const float*)d_in[5], (const float*)d_in[6],
                          (const float*)d_in[7], (const float*)d_in[8],
                          (const float*)d_in[9], (const float*)d_in[10]);
    convBh<<<4096, 256>>>(h);
    convBx<<<dim3(128, 64), dim3(32, 8)>>>(x);

    gemm_fused<<<2048, 128, SMEM_TOTAL>>>(
        c,
        (const float*)d_in[11], (const float*)d_in[12],
        (const float*)d_in[13], (const float*)d_in[14],
        (const float*)d_in[15], (const float*)d_in[16],
        (const float*)d_in[17], (const float*)d_in[18],
        (float*)d_out);
}

// round 15
// speedup vs baseline: 2.2496x; 1.0434x over previous
#include <cuda_runtime.h>
#include <cuda_fp16.h>
#include <cstdint>

#define NIT 64                     // K=4096 in 64-wide slabs
#define A_BYTES 16384              // 128 rows x 128B
#define B_BYTES 16384              // 128 rows x 128B
#define STAGE_BYTES (A_BYTES + B_BYTES)
#define SMEM_TOTAL (3*STAGE_BYTES + 256)   // 98560/CTA -> 2 CTAs/SM
#define SG_STRIDE 130              // epilogue smem row stride (floats)

// g_Ah rows INTERLEAVED: row' = m*4 + gate  (CTA A-tile = contiguous 128 rows)
__device__ __half g_Ah[(size_t)8192 * 4096];
__device__ __half g_Bh[(size_t)4096 * 4096];  // [batch][k] = x^T || h, fp16
__device__ float  g_S[4096];                  // per-batch operand sums (fp32)

__device__ __forceinline__ uint32_t smem_u32(const void* p) {
    uint32_t a;
    asm("{ .reg .u64 t; cvta.to.shared.u64 t, %1; cvt.u32.u64 %0, t; }" : "=r"(a) : "l"(p));
    return a;
}
__device__ __forceinline__ float sigmf(float z) { return 1.0f / (1.0f + __expf(-z)); }

// ---------------- pre-pass ----------------
__global__ void convA(const float* __restrict__ a0, const float* __restrict__ a1,
                      const float* __restrict__ a2, const float* __restrict__ a3,
                      const float* __restrict__ h0, const float* __restrict__ h1,
                      const float* __restrict__ h2, const float* __restrict__ h3) {
    size_t i8 = (size_t)blockIdx.x * 256 + threadIdx.x;
    size_t flat = i8 << 3;
    int rp = (int)(flat >> 12);          // interleaved row = m*4+g
    int k  = (int)(flat & 4095);
    int m = rp >> 2, g = rp & 3;
    const float* w = (k < 2048)
        ? ((g == 0) ? a0 : (g == 1) ? a1 : (g == 2) ? a2 : a3)
        : ((g == 0) ? h0 : (g == 1) ? h1 : (g == 2) ? h2 : h3);
    const float* src = w + (size_t)m * 2048 + (k & 2047);
    float4 v0 = *(const float4*)src;
    float4 v1 = *(const float4*)(src + 4);
    __half h8[8];
    h8[0] = __float2half_rn(v0.x - 0.2f); h8[1] = __float2half_rn(v0.y - 0.2f);
    h8[2] = __float2half_rn(v0.z - 0.2f); h8[3] = __float2half_rn(v0.w - 0.2f);
    h8[4] = __float2half_rn(v1.x - 0.2f); h8[5] = __float2half_rn(v1.y - 0.2f);
    h8[6] = __float2half_rn(v1.z - 0.2f); h8[7] = __float2half_rn(v1.w - 0.2f);
    *(uint4*)(g_Ah + flat) = *(uint4*)h8;
}

__global__ void convBh(const float* __restrict__ h) {
    __shared__ float red[256];
    const int n = blockIdx.x, t = threadIdx.x;
    const float* src = h + (size_t)n * 2048 + t * 8;
    float4 v0 = *(const float4*)src;
    float4 v1 = *(const float4*)(src + 4);
    __half h8[8];
    h8[0] = __float2half_rn(v0.x); h8[1] = __float2half_rn(v0.y);
    h8[2] = __float2half_rn(v0.z); h8[3] = __float2half_rn(v0.w);
    h8[4] = __float2half_rn(v1.x); h8[5] = __float2half_rn(v1.y);
    h8[6] = __float2half_rn(v1.z); h8[7] = __float2half_rn(v1.w);
    *(uint4*)(g_Bh + (size_t)n * 4096 + 2048 + t * 8) = *(uint4*)h8;
    red[t] = ((v0.x + v0.y) + (v0.z + v0.w)) + ((v1.x + v1.y) + (v1.z + v1.w));
    __syncthreads();
    for (int st = 128; st > 0; st >>= 1) {
        if (t < st) red[t] += red[t + st];
        __syncthreads();
    }
    if (t == 0) g_S[n] = red[0];
}

__global__ void convBx(const float* __restrict__ x) {
    __shared__ float t[32][33];
    const int n0 = blockIdx.x << 5, k0 = blockIdx.y << 5;
    const int tx = threadIdx.x, ty = threadIdx.y;
#pragma unroll
    for (int i = 0; i < 4; ++i)
        t[ty + i * 8][tx] = x[(size_t)(k0 + ty + i * 8) * 4096 + n0 + tx];
    __syncthreads();
#pragma unroll
    for (int i = 0; i < 4; ++i) {
        int n = ty + i * 8;
        g_Bh[(size_t)(n0 + n) * 4096 + k0 + tx] = __float2half_rn(t[tx][n]);
    }
    if (ty == 0) {
        float s = 0.0f;
#pragma unroll
        for (int ky = 0; ky < 32; ++ky) s += t[ky][tx];
        atomicAdd(g_S + n0 + tx, s);
    }
}

// ---------------- fused fp16 GEMM + LSTM epilogue ----------------
// CTA: 256 threads (8 warps), tile 128 A-rows x 128 n. Warp tile 64x32.
#define LOAD_STAGE(stg) do { \
    uint32_t da_ = sbase + (uint32_t)(stg) * STAGE_BYTES + dst0; \
    const __half* pa_ = srcA; \
    _Pragma("unroll") \
    for (int q_ = 0; q_ < 4; ++q_) { \
        asm volatile("cp.async.cg.shared.global [%0], [%1], 16;" :: "r"(da_), "l"(pa_)); \
        da_ += 4096; pa_ += (size_t)32 * 4096; \
    } \
    uint32_t db_ = sbase + (uint32_t)(stg) * STAGE_BYTES + A_BYTES + dst0; \
    const __half* pb_ = srcB; \
    _Pragma("unroll") \
    for (int q_ = 0; q_ < 4; ++q_) { \
        asm volatile("cp.async.cg.shared.global [%0], [%1], 16;" :: "r"(db_), "l"(pb_)); \
        db_ += 4096; pb_ += (size_t)32 * 4096; \
    } \
    asm volatile("cp.async.commit_group;"); \
    srcA += 64; srcB += 64; \
} while (0)

#define LDFRAG(ks) do { \
    const int chA_ = (ks) * 2 + akch_l; \
    _Pragma("unroll") \
    for (int i_ = 0; i_ < 4; ++i_) { \
        int row_ = i_ * 16 + arow_l; \
        uint32_t ad_ = sA + (uint32_t)(row_ * 128 + ((chA_ ^ (row_ & 7)) << 4)); \
        asm volatile("ldmatrix.sync.aligned.m8n8.x4.shared.b16 {%0,%1,%2,%3}, [%4];" \
            : "=r"(av[i_][0]), "=r"(av[i_][1]), \
              "=r"(av[i_][2]), "=r"(av[i_][3]) : "r"(ad_)); \
    } \
    const int chB_ = (ks) * 2 + bkch_l; \
    _Pragma("unroll") \
    for (int j_ = 0; j_ < 2; ++j_) { \
        int row_ = brow_l + j_ * 16; \
        uint32_t bd_ = sB + (uint32_t)(row_ * 128 + ((chB_ ^ (row_ & 7)) << 4)); \
        asm volatile("ldmatrix.sync.aligned.m8n8.x4.shared.b16 {%0,%1,%2,%3}, [%4];" \
            : "=r"(bv[j_][0]), "=r"(bv[j_][1]), \
              "=r"(bv[j_][2]), "=r"(bv[j_][3]) : "r"(bd_)); \
    } \
} while (0)

#define DO_MMAS() do { \
    _Pragma("unroll") \
    for (int i_ = 0; i_ < 4; ++i_) \
    _Pragma("unroll") \
    for (int j_ = 0; j_ < 4; ++j_) \
        asm volatile( \
            "mma.sync.aligned.m16n8k16.row.col.f32.f16.f16.f32 " \
            "{%0,%1,%2,%3}, {%4,%5,%6,%7}, {%8,%9}, {%0,%1,%2,%3};" \
            : "+f"(acc[i_][j_][0]), "+f"(acc[i_][j_][1]), \
              "+f"(acc[i_][j_][2]), "+f"(acc[i_][j_][3]) \
            : "r"(av[i_][0]), "r"(av[i_][1]), \
              "r"(av[i_][2]), "r"(av[i_][3]), \
              "r"(bv[j_ >> 1][(j_ & 1) * 2]), \
              "r"(bv[j_ >> 1][(j_ & 1) * 2 + 1])); \
} while (0)

__global__ void __launch_bounds__(256, 2) gemm_fused(
    const float* __restrict__ c_in,
    const float* __restrict__ b_ii, const float* __restrict__ b_hi,
    const float* __restrict__ b_if, const float* __restrict__ b_hf,
    const float* __restrict__ b_ig, const float* __restrict__ b_hg,
    const float* __restrict__ b_io, const float* __restrict__ b_ho,
    float* __restrict__ out)
{
    extern __shared__ char smem[];
    const uint32_t sbase = (smem_u32(smem) + 127u) & ~127u;
    const int tid = threadIdx.x;
    const int bm = blockIdx.x >> 5, bn = blockIdx.x & 31;   // 64 x 32 tiles

    // cp.async bases: 32 rows per pass, 4 passes per operand
    const int r0 = tid >> 3, c0 = tid & 7;
    const uint32_t dst0 = (uint32_t)(r0 * 128 + ((c0 ^ (r0 & 7)) << 4));
    const __half* srcA = g_Ah + (size_t)(bm * 128 + r0) * 4096 + c0 * 8;
    const __half* srcB = g_Bh + (size_t)(bn * 128 + r0) * 4096 + c0 * 8;

    const int lane = tid & 31, wid = tid >> 5;
    const int wm = wid & 1, wn = wid >> 1;            // warp tile 64m x 32n
    const int arow_l = wm * 64 + ((lane >> 3) & 1) * 8 + (lane & 7);
    const int akch_l = lane >> 4;
    const int brow_l = wn * 32 + ((lane >> 4) & 1) * 8 + (lane & 7);
    const int bkch_l = (lane >> 3) & 1;

    float acc[4][4][4];
#pragma unroll
    for (int i = 0; i < 4; ++i)
#pragma unroll
        for (int j = 0; j < 4; ++j)
#pragma unroll
            for (int r = 0; r < 4; ++r) acc[i][j][r] = 0.0f;

    uint32_t av[4][4], bv[2][4];

    LOAD_STAGE(0);
    LOAD_STAGE(1);

    for (int it = 0; it < NIT; ++it) {
        if (it + 1 < NIT) asm volatile("cp.async.wait_group 1;");
        else              asm volatile("cp.async.wait_group 0;");
        __syncthreads();

        const uint32_t sA = sbase + (uint32_t)(it % 3) * STAGE_BYTES;
        const uint32_t sB = sA + A_BYTES;

        LDFRAG(0);
        if (it + 2 < NIT) LOAD_STAGE((it + 2) % 3);
        DO_MMAS();
        LDFRAG(1); DO_MMAS();
        LDFRAG(2); DO_MMAS();
        LDFRAG(3); DO_MMAS();
    }
    __syncthreads();

    // ---- stage gates: local A-row = m*4+gate -> sG[gate][32 m][128 n] ----
    float* sG = (float*)smem;
    {
        const int rbase = lane >> 2;
        const int col = wn * 32 + (lane & 3) * 2;
#pragma unroll
        for (int i = 0; i < 4; ++i)
#pragma unroll
            for (int rr = 0; rr < 2; ++rr) {
                int row = wm * 64 + i * 16 + rbase + rr * 8;
                float* p = sG + (size_t)(row & 3) * 32 * SG_STRIDE
                              + (row >> 2) * SG_STRIDE + col;
#pragma unroll
                for (int j = 0; j < 4; ++j)
                    *(float2*)(p + j * 8) =
                        make_float2(acc[i][j][rr * 2], acc[i][j][rr * 2 + 1]);
            }
    }
    __syncthreads();

    // ---- LSTM epilogue, coalesced along m (warp = 32 consecutive m) ----
    const int m_l = tid & 31, nq = tid >> 5;
    const int m_g = bm * 32 + m_l;
    const float bsi = b_ii[m_g] + b_hi[m_g];
    const float bsf = b_if[m_g] + b_hf[m_g];
    const float bsg = b_ig[m_g] + b_hg[m_g];
    const float bso = b_io[m_g] + b_ho[m_g];
    float* out_c = out + (size_t)4096 * 2048;
    const float* row0 = sG + m_l * SG_STRIDE;
#pragma unroll 4
    for (int loop = 0; loop < 16; ++loop) {
        const int n_l = loop * 8 + nq;
        const int n_g = bn * 128 + n_l;
        const float s2 = 0.2f * g_S[n_g];
        float iv = sigmf(row0[0 * 32 * SG_STRIDE + n_l] + s2 + bsi);
        float fv = sigmf(row0[1 * 32 * SG_STRIDE + n_l] + s2 + bsf);
        float gv = tanhf(row0[2 * 32 * SG_STRIDE + n_l] + s2 + bsg);
        float ov = sigmf(row0[3 * 32 * SG_STRIDE + n_l] + s2 + bso);
        float cv = c_in[(size_t)n_g * 2048 + m_g];
        float cn = fv * cv + iv * gv;
        out_c[(size_t)n_g * 2048 + m_g] = cn;
        out[(size_t)n_g * 2048 + m_g]   = ov * tanhf(cn);
    }
}

// ---------------- launcher ----------------
extern "C" void kernel_launch(void* const* d_in, const int* in_sizes, int n_in,
                              void* d_out, int out_size)
{
    (void)in_sizes; (void)n_in; (void)out_size;
    const float* x = (const float*)d_in[0];
    const float* h = (const float*)d_in[1];
    const float* c = (const float*)d_in[2];

    cudaFuncSetAttribute(gemm_fused, cudaFuncAttributeMaxDynamicSharedMemorySize, SMEM_TOTAL);

    convA<<<16384, 256>>>((const float*)d_in[3], (const float*)d_in[4],
                          (const float*)d_in[5], (const float*)d_in[6],
                          (const float*)d_in[7], (const float*)d_in[8],
                          (const float*)d_in[9], (const float*)d_in[10]);
    convBh<<<4096, 256>>>(h);
    convBx<<<dim3(128, 64), dim3(32, 8)>>>(x);

    gemm_fused<<<2048, 256, SMEM_TOTAL>>>(
        c,
        (const float*)d_in[11], (const float*)d_in[12],
        (const float*)d_in[13], (const float*)d_in[14],
        (const float*)d_in[15], (const float*)d_in[16],
        (const float*)d_in[17], (const float*)d_in[18],
        (float*)d_out);
}